// round 12
// baseline (speedup 1.0000x reference)
#include <cuda_runtime.h>
#include <math.h>

// Problem constants
#define U_    128
#define NG    512
#define T_    512
#define B_    256
#define F_    64
#define OUT_  6

// k-split LSTM: per (column, k-half): 32 floats in SMEM, 32 in registers
#define KS2   32           // SMEM floats per column-half
#define KR2   32           // register floats per column-half
#define RSTRIDE 36         // padded slice stride (144B): 16B-granule offsets 9l mod 8 -> conflict-free

typedef unsigned long long ull;

#define FMA2U(acc, a, b) \
    asm("fma.rn.f32x2 %0, %1, %2, %0;" : "+l"(acc) : "l"(a), "l"(b))

__device__ __forceinline__ ull dup2(float x) {
    ull r;
    asm("mov.b64 %0, {%1, %1};" : "=l"(r) : "f"(x));
    return r;
}
__device__ __forceinline__ float lo32(ull v) { return __int_as_float((int)(v & 0xffffffffull)); }
__device__ __forceinline__ float hi32(ull v) { return __int_as_float((int)(v >> 32)); }
__device__ __forceinline__ float unpack_sum(ull v) { return lo32(v) + hi32(v); }

__device__ __forceinline__ float fast_sigmoid(float x) {
    return __fdividef(1.f, 1.f + __expf(-x));
}
__device__ __forceinline__ float fast_tanh(float x) {
    float e = __expf(fminf(-2.f * x, 80.f));
    return __fdividef(1.f - e, 1.f + e);
}

// ---------------- scratch ----------------
__device__ float g_xw[(size_t)B_ * T_ * NG];
__device__ float g_h [(size_t)B_ * T_ * U_];
__device__ float g_RT[3][NG * U_];

// ---------------- R transpose ----------------
__global__ void k_transpose_R(const float* __restrict__ R, int layer) {
    int j = blockIdx.x;
    int k = threadIdx.x;
    g_RT[layer][j * U_ + k] = R[k * NG + j];
}

// ---------------- GEMM (unchanged) ----------------
#define GBM 128
#define GBN 128
#define GBK 8
#define GPAD 4
__global__ __launch_bounds__(256) void k_gemm_xw(const float* __restrict__ Ain,
                                                 const float* __restrict__ W,
                                                 const float* __restrict__ bias,
                                                 int K) {
    const float* A = Ain ? Ain : g_h;
    __shared__ float As[GBK][GBM + GPAD];
    __shared__ float Bs[GBK][GBN + GPAD];
    const int brow = blockIdx.y * GBM;
    const int bcol = blockIdx.x * GBN;
    const int tid = threadIdx.x;
    const int tx = tid & 15;
    const int ty = tid >> 4;

    const int a_m  = tid >> 1;
    const int a_kq = (tid & 1) * 4;
    const int b_k  = tid >> 5;
    const int b_n  = (tid & 31) * 4;

    ull acc2[8][4];
    #pragma unroll
    for (int i = 0; i < 8; i++)
        #pragma unroll
        for (int j = 0; j < 4; j++) acc2[i][j] = 0ull;

    for (int k0 = 0; k0 < K; k0 += GBK) {
        float4 av = *reinterpret_cast<const float4*>(&A[(size_t)(brow + a_m) * K + (k0 + a_kq)]);
        As[a_kq + 0][a_m] = av.x;
        As[a_kq + 1][a_m] = av.y;
        As[a_kq + 2][a_m] = av.z;
        As[a_kq + 3][a_m] = av.w;
        *reinterpret_cast<float4*>(&Bs[b_k][b_n]) =
            *reinterpret_cast<const float4*>(&W[(size_t)(k0 + b_k) * NG + (bcol + b_n)]);
        __syncthreads();

        #pragma unroll
        for (int k = 0; k < GBK; k++) {
            float4 a0 = *reinterpret_cast<const float4*>(&As[k][ty * 8]);
            float4 a1 = *reinterpret_cast<const float4*>(&As[k][ty * 8 + 4]);
            ulonglong2 bv0 = *reinterpret_cast<const ulonglong2*>(&Bs[k][tx * 8]);
            ulonglong2 bv1 = *reinterpret_cast<const ulonglong2*>(&Bs[k][tx * 8 + 4]);
            ull ad;
            ad = dup2(a0.x);
            FMA2U(acc2[0][0], ad, bv0.x); FMA2U(acc2[0][1], ad, bv0.y);
            FMA2U(acc2[0][2], ad, bv1.x); FMA2U(acc2[0][3], ad, bv1.y);
            ad = dup2(a0.y);
            FMA2U(acc2[1][0], ad, bv0.x); FMA2U(acc2[1][1], ad, bv0.y);
            FMA2U(acc2[1][2], ad, bv1.x); FMA2U(acc2[1][3], ad, bv1.y);
            ad = dup2(a0.z);
            FMA2U(acc2[2][0], ad, bv0.x); FMA2U(acc2[2][1], ad, bv0.y);
            FMA2U(acc2[2][2], ad, bv1.x); FMA2U(acc2[2][3], ad, bv1.y);
            ad = dup2(a0.w);
            FMA2U(acc2[3][0], ad, bv0.x); FMA2U(acc2[3][1], ad, bv0.y);
            FMA2U(acc2[3][2], ad, bv1.x); FMA2U(acc2[3][3], ad, bv1.y);
            ad = dup2(a1.x);
            FMA2U(acc2[4][0], ad, bv0.x); FMA2U(acc2[4][1], ad, bv0.y);
            FMA2U(acc2[4][2], ad, bv1.x); FMA2U(acc2[4][3], ad, bv1.y);
            ad = dup2(a1.y);
            FMA2U(acc2[5][0], ad, bv0.x); FMA2U(acc2[5][1], ad, bv0.y);
            FMA2U(acc2[5][2], ad, bv1.x); FMA2U(acc2[5][3], ad, bv1.y);
            ad = dup2(a1.z);
            FMA2U(acc2[6][0], ad, bv0.x); FMA2U(acc2[6][1], ad, bv0.y);
            FMA2U(acc2[6][2], ad, bv1.x); FMA2U(acc2[6][3], ad, bv1.y);
            ad = dup2(a1.w);
            FMA2U(acc2[7][0], ad, bv0.x); FMA2U(acc2[7][1], ad, bv0.y);
            FMA2U(acc2[7][2], ad, bv1.x); FMA2U(acc2[7][3], ad, bv1.y);
        }
        __syncthreads();
    }

    const int col0 = bcol + tx * 8;
    float bb[8];
    #pragma unroll
    for (int j = 0; j < 8; j++) bb[j] = bias[col0 + j];
    #pragma unroll
    for (int i = 0; i < 8; i++) {
        size_t row = (size_t)(brow + ty * 8 + i);
        float4 o0, o1;
        o0.x = lo32(acc2[i][0]) + bb[0]; o0.y = hi32(acc2[i][0]) + bb[1];
        o0.z = lo32(acc2[i][1]) + bb[2]; o0.w = hi32(acc2[i][1]) + bb[3];
        o1.x = lo32(acc2[i][2]) + bb[4]; o1.y = hi32(acc2[i][2]) + bb[5];
        o1.z = lo32(acc2[i][3]) + bb[6]; o1.w = hi32(acc2[i][3]) + bb[7];
        *reinterpret_cast<float4*>(&g_xw[row * NG + col0])     = o0;
        *reinterpret_cast<float4*>(&g_xw[row * NG + col0 + 4]) = o1;
    }
}

// ---------------- LSTM scan: k-split, 512 threads, 16 warps ----------------
// Thread (c = tid>>1, s = tid&1) computes k-half s of columns {c, c+256} x 2 rows.
// Halves combined with shfl_xor(1). 64 R-floats/thread (32 SMEM + 32 regs).
#define LSTM_SMEM_FLOATS (2 * NG * RSTRIDE + 2 * U_ + 2 * NG)
#define LSTM_SMEM_BYTES  (LSTM_SMEM_FLOATS * 4)

__global__ __launch_bounds__(512, 1) void k_lstm(int layer) {
    extern __shared__ float smem[];
    float* sR   = smem;                        // [1024][RSTRIDE] slices (col*2+s)
    float* sh   = sR + 2 * NG * RSTRIDE;       // [2*U_] current h (row0,row1)
    float* sact = sh + 2 * U_;                 // [2][512]

    const int tid = threadIdx.x;               // 0..511
    const int c   = tid >> 1;                  // 0..255
    const int s   = tid & 1;                   // k-half
    const int c0  = c;
    const int c1  = c + 256;
    const int ks  = s * 64;
    const int b0  = blockIdx.x * 2;
    const float* RT = g_RT[layer];

    // SMEM R: slice (col*2+s2) holds RT[col][s2*64 .. s2*64+32)
    for (int i = tid; i < 2 * NG * KS2; i += 512) {
        int slice = i / KS2, k = i - slice * KS2;
        int col = slice >> 1, s2 = slice & 1;
        sR[slice * RSTRIDE + k] = RT[col * U_ + s2 * 64 + k];
    }
    // register R: k in [ks+32, ks+64) for both columns (16 ull each)
    ull rr0[KR2 / 2], rr1[KR2 / 2];
    {
        const ulonglong2* rg0 = reinterpret_cast<const ulonglong2*>(RT + c0 * U_ + ks + KS2);
        const ulonglong2* rg1 = reinterpret_cast<const ulonglong2*>(RT + c1 * U_ + ks + KS2);
        #pragma unroll
        for (int q = 0; q < KR2 / 4; q++) {
            ulonglong2 v0 = rg0[q];
            ulonglong2 v1 = rg1[q];
            rr0[2 * q] = v0.x; rr0[2 * q + 1] = v0.y;
            rr1[2 * q] = v1.x; rr1[2 * q + 1] = v1.y;
        }
    }
    if (tid < 2 * U_) sh[tid] = 0.f;
    __syncthreads();

    const ulonglong2* rs0 = reinterpret_cast<const ulonglong2*>(sR + (2 * c0 + s) * RSTRIDE);
    const ulonglong2* rs1 = reinterpret_cast<const ulonglong2*>(sR + (2 * c1 + s) * RSTRIDE);
    const ulonglong2* h0p = reinterpret_cast<const ulonglong2*>(sh + ks);        // row0, this k-half
    const ulonglong2* h1p = reinterpret_cast<const ulonglong2*>(sh + U_ + ks);   // row1

    const size_t xw0base = (size_t)b0 * T_ * NG;
    const size_t xw1base = (size_t)(b0 + 1) * T_ * NG;

    float creg = 0.f;                           // cell state (valid for tid<256)

    float pf00 = 0.f, pf01 = 0.f, pf10 = 0.f, pf11 = 0.f;
    if (s == 0) {
        pf00 = __ldcs(&g_xw[xw0base + c0]);
        pf01 = __ldcs(&g_xw[xw0base + c1]);
        pf10 = __ldcs(&g_xw[xw1base + c0]);
        pf11 = __ldcs(&g_xw[xw1base + c1]);
    }

    for (int t = 0; t < T_; t++) {
        ull a00 = (ull)__float_as_uint(pf00);   // s==1 threads start from 0
        ull a01 = (ull)__float_as_uint(pf01);
        ull a10 = (ull)__float_as_uint(pf10);
        ull a11 = (ull)__float_as_uint(pf11);
        if (s == 0 && t + 1 < T_) {
            size_t o0 = xw0base + (size_t)(t + 1) * NG;
            size_t o1 = xw1base + (size_t)(t + 1) * NG;
            pf00 = __ldcs(&g_xw[o0 + c0]);
            pf01 = __ldcs(&g_xw[o0 + c1]);
            pf10 = __ldcs(&g_xw[o1 + c0]);
            pf11 = __ldcs(&g_xw[o1 + c1]);
        }

        // SMEM R part: k in [ks, ks+32)
        #pragma unroll
        for (int q = 0; q < KS2 / 4; q++) {
            ulonglong2 r0 = rs0[q];
            ulonglong2 r1 = rs1[q];
            ulonglong2 h0 = h0p[q];
            ulonglong2 h1 = h1p[q];
            FMA2U(a00, r0.x, h0.x); FMA2U(a00, r0.y, h0.y);
            FMA2U(a01, r1.x, h0.x); FMA2U(a01, r1.y, h0.y);
            FMA2U(a10, r0.x, h1.x); FMA2U(a10, r0.y, h1.y);
            FMA2U(a11, r1.x, h1.x); FMA2U(a11, r1.y, h1.y);
        }
        // register R part: k in [ks+32, ks+64)
        #pragma unroll
        for (int q = 0; q < KR2 / 4; q++) {
            ulonglong2 h0 = h0p[KS2 / 4 + q];
            ulonglong2 h1 = h1p[KS2 / 4 + q];
            FMA2U(a00, rr0[2 * q], h0.x); FMA2U(a00, rr0[2 * q + 1], h0.y);
            FMA2U(a01, rr1[2 * q], h0.x); FMA2U(a01, rr1[2 * q + 1], h0.y);
            FMA2U(a10, rr0[2 * q], h1.x); FMA2U(a10, rr0[2 * q + 1], h1.y);
            FMA2U(a11, rr1[2 * q], h1.x); FMA2U(a11, rr1[2 * q + 1], h1.y);
        }

        // combine k-halves (partner = lane^1)
        float z00 = unpack_sum(a00); z00 += __shfl_xor_sync(0xffffffffu, z00, 1);
        float z01 = unpack_sum(a01); z01 += __shfl_xor_sync(0xffffffffu, z01, 1);
        float z10 = unpack_sum(a10); z10 += __shfl_xor_sync(0xffffffffu, z10, 1);
        float z11 = unpack_sum(a11); z11 += __shfl_xor_sync(0xffffffffu, z11, 1);

        if (s == 0) {
            float s00 = fast_sigmoid(z00);      // c0: i (c<128) or f gate
            float s10 = fast_sigmoid(z10);
            float s01, s11;                     // c1: g (c<128, tanh) or o (sigmoid)
            if (c < 128) { s01 = fast_tanh(z01);    s11 = fast_tanh(z11); }
            else         { s01 = fast_sigmoid(z01); s11 = fast_sigmoid(z11); }
            sact[c0] = s00;        sact[c1] = s01;
            sact[NG + c0] = s10;   sact[NG + c1] = s11;
        }
        __syncthreads();

        if (tid < 2 * U_) {                     // cell update: thread owns (m,u)
            int m = tid >> 7, u = tid & (U_ - 1);
            const float* sg = sact + m * NG;
            float iv = sg[u], fv = sg[U_ + u], gv = sg[2 * U_ + u], ov = sg[3 * U_ + u];
            creg = fmaf(fv, creg, iv * gv);
            float h = ov * fast_tanh(creg);
            sh[m * U_ + u] = h;
            g_h[((size_t)(b0 + m) * T_ + t) * U_ + u] = h;
        }
        __syncthreads();
    }
}

// ---------------- dense head ----------------
__global__ void k_dense(const float* __restrict__ Wd, const float* __restrict__ bd,
                        float* __restrict__ out) {
    int idx = blockIdx.x * 256 + threadIdx.x;
    if (idx >= B_ * OUT_) return;
    int b = idx / OUT_, j = idx % OUT_;
    const float* hrow = &g_h[((size_t)b * T_ + (T_ - 1)) * U_];
    float s = bd[j];
    #pragma unroll
    for (int k = 0; k < U_; k++) s = fmaf(hrow[k], Wd[k * OUT_ + j], s);
    out[idx] = s;
}

// ---------------- launch ----------------
extern "C" void kernel_launch(void* const* d_in, const int* in_sizes, int n_in,
                              void* d_out, int out_size) {
    const float* x  = (const float*)d_in[0];
    const float* W0 = (const float*)d_in[1];
    const float* R0 = (const float*)d_in[2];
    const float* b0 = (const float*)d_in[3];
    const float* W1 = (const float*)d_in[4];
    const float* R1 = (const float*)d_in[5];
    const float* b1 = (const float*)d_in[6];
    const float* W2 = (const float*)d_in[7];
    const float* R2 = (const float*)d_in[8];
    const float* b2 = (const float*)d_in[9];
    const float* Wd = (const float*)d_in[10];
    const float* bd = (const float*)d_in[11];
    float* out = (float*)d_out;

    cudaFuncSetAttribute(k_lstm, cudaFuncAttributeMaxDynamicSharedMemorySize, LSTM_SMEM_BYTES);

    dim3 gemm_grid(NG / GBN, (B_ * T_) / GBM);

    // launch order keeps ncu's capture slot (index 3) on k_lstm
    k_transpose_R<<<NG, U_>>>(R0, 0);
    k_gemm_xw<<<gemm_grid, 256>>>(x, W0, b0, F_);
    k_transpose_R<<<NG, U_>>>(R1, 1);
    k_lstm<<<B_ / 2, 512, LSTM_SMEM_BYTES>>>(0);
    k_transpose_R<<<NG, U_>>>(R2, 2);

    k_gemm_xw<<<gemm_grid, 256>>>(nullptr, W1, b1, U_);
    k_lstm<<<B_ / 2, 512, LSTM_SMEM_BYTES>>>(1);

    k_gemm_xw<<<gemm_grid, 256>>>(nullptr, W2, b2, U_);
    k_lstm<<<B_ / 2, 512, LSTM_SMEM_BYTES>>>(2);

    k_dense<<<(B_ * OUT_ + 255) / 256, 256>>>(Wd, bd, out);
}

// round 13
// speedup vs baseline: 1.2486x; 1.2486x over previous
#include <cuda_runtime.h>
#include <math.h>

// Problem constants
#define U_    128
#define NG    512
#define T_    512
#define B_    256
#define F_    64
#define OUT_  6

// LSTM R split (R11 proven config): 44 k-values in SMEM, 84 in registers
#define KSM   44
#define KRG   84
#define NQ_SM (KSM / 4)    // 11
#define NQ_RG (KRG / 4)    // 21

typedef unsigned long long ull;

#define FMA2U(acc, a, b) \
    asm("fma.rn.f32x2 %0, %1, %2, %0;" : "+l"(acc) : "l"(a), "l"(b))
#define FMA2(acc, a, b) \
    asm("fma.rn.f32x2 %0, %1, %2, %0;" : "+l"(acc) \
        : "l"(__double_as_longlong(a)), "l"(__double_as_longlong(b)))

__device__ __forceinline__ ull dup2(float x) {
    ull r;
    asm("mov.b64 %0, {%1, %1};" : "=l"(r) : "f"(x));
    return r;
}
__device__ __forceinline__ float lo32(ull v) { return __int_as_float((int)(v & 0xffffffffull)); }
__device__ __forceinline__ float hi32(ull v) { return __int_as_float((int)(v >> 32)); }
__device__ __forceinline__ float unpack_sum(ull v) { return lo32(v) + hi32(v); }

__device__ __forceinline__ float fast_sigmoid(float x) {
    return __fdividef(1.f, 1.f + __expf(-x));
}
__device__ __forceinline__ float fast_tanh(float x) {
    float e = __expf(fminf(-2.f * x, 80.f));
    return __fdividef(1.f - e, 1.f + e);
}

// ---------------- scratch ----------------
__device__ float g_xw[(size_t)B_ * T_ * NG];
__device__ float g_h [(size_t)B_ * T_ * U_];
__device__ float g_RT[3][NG * U_];

// ---------------- R transpose ----------------
__global__ void k_transpose_R(const float* __restrict__ R, int layer) {
    int j = blockIdx.x;
    int k = threadIdx.x;
    g_RT[layer][j * U_ + k] = R[k * NG + j];
}

// ---------------- GEMM: double-buffered 128x128x16 ----------------
#define GBM 128
#define GBN 128
#define BK2 16
#define GPAD 4
__global__ __launch_bounds__(256) void k_gemm_xw(const float* __restrict__ Ain,
                                                 const float* __restrict__ W,
                                                 const float* __restrict__ bias,
                                                 int K) {
    const float* A = Ain ? Ain : g_h;
    __shared__ float As[2][BK2][GBM + GPAD];
    __shared__ float Bs[2][BK2][GBN + GPAD];
    const int brow = blockIdx.y * GBM;
    const int bcol = blockIdx.x * GBN;
    const int tid = threadIdx.x;
    const int tx = tid & 15;
    const int ty = tid >> 4;

    // A tile loads: row = tid>>1 (0..127), k offset = (tid&1)*8 (two float4)
    const int a_m = tid >> 1;
    const int a_k = (tid & 1) * 8;
    // B tile loads: k rows tid>>5 and tid>>5+8, n = (tid&31)*4
    const int b_k = tid >> 5;
    const int b_n = (tid & 31) * 4;

    ull acc2[8][4];
    #pragma unroll
    for (int i = 0; i < 8; i++)
        #pragma unroll
        for (int j = 0; j < 4; j++) acc2[i][j] = 0ull;

    const float* a_ptr = &A[(size_t)(brow + a_m) * K + a_k];
    const float* b_ptr0 = &W[(size_t)b_k * NG + bcol + b_n];
    const float* b_ptr1 = &W[(size_t)(b_k + 8) * NG + bcol + b_n];

    // prologue: load k-block 0 into buffer 0
    float4 ar0 = *reinterpret_cast<const float4*>(a_ptr);
    float4 ar1 = *reinterpret_cast<const float4*>(a_ptr + 4);
    float4 br0 = *reinterpret_cast<const float4*>(b_ptr0);
    float4 br1 = *reinterpret_cast<const float4*>(b_ptr1);
    As[0][a_k + 0][a_m] = ar0.x; As[0][a_k + 1][a_m] = ar0.y;
    As[0][a_k + 2][a_m] = ar0.z; As[0][a_k + 3][a_m] = ar0.w;
    As[0][a_k + 4][a_m] = ar1.x; As[0][a_k + 5][a_m] = ar1.y;
    As[0][a_k + 6][a_m] = ar1.z; As[0][a_k + 7][a_m] = ar1.w;
    *reinterpret_cast<float4*>(&Bs[0][b_k][b_n])     = br0;
    *reinterpret_cast<float4*>(&Bs[0][b_k + 8][b_n]) = br1;
    __syncthreads();

    const int nk = K / BK2;
    for (int kb = 0; kb < nk; kb++) {
        const int cur = kb & 1;
        const int nxt = cur ^ 1;
        if (kb + 1 < nk) {
            const int k0 = (kb + 1) * BK2;
            ar0 = *reinterpret_cast<const float4*>(a_ptr + k0);
            ar1 = *reinterpret_cast<const float4*>(a_ptr + k0 + 4);
            br0 = *reinterpret_cast<const float4*>(b_ptr0 + (size_t)k0 * NG);
            br1 = *reinterpret_cast<const float4*>(b_ptr1 + (size_t)k0 * NG);
        }

        #pragma unroll
        for (int k = 0; k < BK2; k++) {
            float4 a0 = *reinterpret_cast<const float4*>(&As[cur][k][ty * 8]);
            float4 a1 = *reinterpret_cast<const float4*>(&As[cur][k][ty * 8 + 4]);
            ulonglong2 bv0 = *reinterpret_cast<const ulonglong2*>(&Bs[cur][k][tx * 8]);
            ulonglong2 bv1 = *reinterpret_cast<const ulonglong2*>(&Bs[cur][k][tx * 8 + 4]);
            ull ad;
            ad = dup2(a0.x);
            FMA2U(acc2[0][0], ad, bv0.x); FMA2U(acc2[0][1], ad, bv0.y);
            FMA2U(acc2[0][2], ad, bv1.x); FMA2U(acc2[0][3], ad, bv1.y);
            ad = dup2(a0.y);
            FMA2U(acc2[1][0], ad, bv0.x); FMA2U(acc2[1][1], ad, bv0.y);
            FMA2U(acc2[1][2], ad, bv1.x); FMA2U(acc2[1][3], ad, bv1.y);
            ad = dup2(a0.z);
            FMA2U(acc2[2][0], ad, bv0.x); FMA2U(acc2[2][1], ad, bv0.y);
            FMA2U(acc2[2][2], ad, bv1.x); FMA2U(acc2[2][3], ad, bv1.y);
            ad = dup2(a0.w);
            FMA2U(acc2[3][0], ad, bv0.x); FMA2U(acc2[3][1], ad, bv0.y);
            FMA2U(acc2[3][2], ad, bv1.x); FMA2U(acc2[3][3], ad, bv1.y);
            ad = dup2(a1.x);
            FMA2U(acc2[4][0], ad, bv0.x); FMA2U(acc2[4][1], ad, bv0.y);
            FMA2U(acc2[4][2], ad, bv1.x); FMA2U(acc2[4][3], ad, bv1.y);
            ad = dup2(a1.y);
            FMA2U(acc2[5][0], ad, bv0.x); FMA2U(acc2[5][1], ad, bv0.y);
            FMA2U(acc2[5][2], ad, bv1.x); FMA2U(acc2[5][3], ad, bv1.y);
            ad = dup2(a1.z);
            FMA2U(acc2[6][0], ad, bv0.x); FMA2U(acc2[6][1], ad, bv0.y);
            FMA2U(acc2[6][2], ad, bv1.x); FMA2U(acc2[6][3], ad, bv1.y);
            ad = dup2(a1.w);
            FMA2U(acc2[7][0], ad, bv0.x); FMA2U(acc2[7][1], ad, bv0.y);
            FMA2U(acc2[7][2], ad, bv1.x); FMA2U(acc2[7][3], ad, bv1.y);
        }

        if (kb + 1 < nk) {
            As[nxt][a_k + 0][a_m] = ar0.x; As[nxt][a_k + 1][a_m] = ar0.y;
            As[nxt][a_k + 2][a_m] = ar0.z; As[nxt][a_k + 3][a_m] = ar0.w;
            As[nxt][a_k + 4][a_m] = ar1.x; As[nxt][a_k + 5][a_m] = ar1.y;
            As[nxt][a_k + 6][a_m] = ar1.z; As[nxt][a_k + 7][a_m] = ar1.w;
            *reinterpret_cast<float4*>(&Bs[nxt][b_k][b_n])     = br0;
            *reinterpret_cast<float4*>(&Bs[nxt][b_k + 8][b_n]) = br1;
        }
        __syncthreads();
    }

    const int col0 = bcol + tx * 8;
    float bb[8];
    #pragma unroll
    for (int j = 0; j < 8; j++) bb[j] = bias[col0 + j];
    #pragma unroll
    for (int i = 0; i < 8; i++) {
        size_t row = (size_t)(brow + ty * 8 + i);
        float4 o0, o1;
        o0.x = lo32(acc2[i][0]) + bb[0]; o0.y = hi32(acc2[i][0]) + bb[1];
        o0.z = lo32(acc2[i][1]) + bb[2]; o0.w = hi32(acc2[i][1]) + bb[3];
        o1.x = lo32(acc2[i][2]) + bb[4]; o1.y = hi32(acc2[i][2]) + bb[5];
        o1.z = lo32(acc2[i][3]) + bb[6]; o1.w = hi32(acc2[i][3]) + bb[7];
        *reinterpret_cast<float4*>(&g_xw[row * NG + col0])     = o0;
        *reinterpret_cast<float4*>(&g_xw[row * NG + col0 + 4]) = o1;
    }
}

// ---------------- LSTM scan (R11 exact: KSM=44/KRG=84, 256 thr, SMEM pad) ----------------
#define LSTM_SMEM_FLOATS 30000
#define LSTM_SMEM_BYTES  (LSTM_SMEM_FLOATS * 4)

__global__ __launch_bounds__(256) void k_lstm(int layer) {
    extern __shared__ float smem[];
    float* sR   = smem;                       // [512][KSM]
    float* sh   = sR + NG * KSM;              // [2][128]
    float* sc   = sh + 2 * U_;                // [2][128]
    float* sact = sc + 2 * U_;                // [2][512]

    const int tid = threadIdx.x;
    const int c0 = tid;
    const int c1 = tid + 256;
    const int b0 = blockIdx.x * 2;
    const float* RT = g_RT[layer];

    for (int i = tid; i < NG * KSM; i += 256) {
        int col = i / KSM, k = i - col * KSM;
        sR[i] = RT[col * U_ + k];
    }
    double rr0[NQ_RG * 2], rr1[NQ_RG * 2];
    {
        const double2* rg0 = reinterpret_cast<const double2*>(RT + c0 * U_ + KSM);
        const double2* rg1 = reinterpret_cast<const double2*>(RT + c1 * U_ + KSM);
        #pragma unroll
        for (int q = 0; q < NQ_RG; q++) {
            double2 v0 = rg0[q];
            double2 v1 = rg1[q];
            rr0[2 * q] = v0.x; rr0[2 * q + 1] = v0.y;
            rr1[2 * q] = v1.x; rr1[2 * q + 1] = v1.y;
        }
    }
    { sh[tid] = 0.f; sc[tid] = 0.f; }
    __syncthreads();

    const double2* rs0 = reinterpret_cast<const double2*>(sR + c0 * KSM);
    const double2* rs1 = reinterpret_cast<const double2*>(sR + c1 * KSM);
    const double2* h0p = reinterpret_cast<const double2*>(sh);
    const double2* h1p = reinterpret_cast<const double2*>(sh + U_);
    const size_t xw0base = (size_t)b0 * T_ * NG;
    const size_t xw1base = (size_t)(b0 + 1) * T_ * NG;

    float pf00 = __ldcs(&g_xw[xw0base + c0]);
    float pf01 = __ldcs(&g_xw[xw0base + c1]);
    float pf10 = __ldcs(&g_xw[xw1base + c0]);
    float pf11 = __ldcs(&g_xw[xw1base + c1]);

    for (int t = 0; t < T_; t++) {
        ull a00 = (ull)__float_as_uint(pf00);
        ull a01 = (ull)__float_as_uint(pf01);
        ull a10 = (ull)__float_as_uint(pf10);
        ull a11 = (ull)__float_as_uint(pf11);
        if (t + 1 < T_) {
            size_t o0 = xw0base + (size_t)(t + 1) * NG;
            size_t o1 = xw1base + (size_t)(t + 1) * NG;
            pf00 = __ldcs(&g_xw[o0 + c0]);
            pf01 = __ldcs(&g_xw[o0 + c1]);
            pf10 = __ldcs(&g_xw[o1 + c0]);
            pf11 = __ldcs(&g_xw[o1 + c1]);
        }

        #pragma unroll
        for (int q = 0; q < NQ_SM; q++) {
            double2 r0 = rs0[q];
            double2 r1 = rs1[q];
            double2 h0 = h0p[q];
            double2 h1 = h1p[q];
            FMA2(a00, r0.x, h0.x); FMA2(a01, r1.x, h0.x);
            FMA2(a10, r0.x, h1.x); FMA2(a11, r1.x, h1.x);
            FMA2(a00, r0.y, h0.y); FMA2(a01, r1.y, h0.y);
            FMA2(a10, r0.y, h1.y); FMA2(a11, r1.y, h1.y);
        }
        #pragma unroll
        for (int q = 0; q < NQ_RG; q++) {
            double2 h0 = h0p[NQ_SM + q];
            double2 h1 = h1p[NQ_SM + q];
            FMA2(a00, rr0[2 * q], h0.x); FMA2(a01, rr1[2 * q], h0.x);
            FMA2(a10, rr0[2 * q], h1.x); FMA2(a11, rr1[2 * q], h1.x);
            FMA2(a00, rr0[2 * q + 1], h0.y); FMA2(a01, rr1[2 * q + 1], h0.y);
            FMA2(a10, rr0[2 * q + 1], h1.y); FMA2(a11, rr1[2 * q + 1], h1.y);
        }

        float z00 = unpack_sum(a00);
        float z01 = unpack_sum(a01);
        float z10 = unpack_sum(a10);
        float z11 = unpack_sum(a11);

        float s00 = fast_sigmoid(z00);
        float s10 = fast_sigmoid(z10);
        float s01, s11;
        if (tid < 128) { s01 = fast_tanh(z01);    s11 = fast_tanh(z11); }
        else           { s01 = fast_sigmoid(z01); s11 = fast_sigmoid(z11); }

        sact[c0] = s00;        sact[c1] = s01;
        sact[NG + c0] = s10;   sact[NG + c1] = s11;
        __syncthreads();

        {
            int m = tid >> 7, u = tid & (U_ - 1);
            const float* s = sact + m * NG;
            float iv = s[u], fv = s[U_ + u], gv = s[2 * U_ + u], ov = s[3 * U_ + u];
            float c = fmaf(fv, sc[tid], iv * gv);
            float h = ov * fast_tanh(c);
            sc[tid] = c;
            sh[m * U_ + u] = h;
            g_h[((size_t)(b0 + m) * T_ + t) * U_ + u] = h;
        }
        __syncthreads();
    }
}

// ---------------- dense head ----------------
__global__ void k_dense(const float* __restrict__ Wd, const float* __restrict__ bd,
                        float* __restrict__ out) {
    int idx = blockIdx.x * 256 + threadIdx.x;
    if (idx >= B_ * OUT_) return;
    int b = idx / OUT_, j = idx % OUT_;
    const float* hrow = &g_h[((size_t)b * T_ + (T_ - 1)) * U_];
    float s = bd[j];
    #pragma unroll
    for (int k = 0; k < U_; k++) s = fmaf(hrow[k], Wd[k * OUT_ + j], s);
    out[idx] = s;
}

// ---------------- launch ----------------
extern "C" void kernel_launch(void* const* d_in, const int* in_sizes, int n_in,
                              void* d_out, int out_size) {
    const float* x  = (const float*)d_in[0];
    const float* W0 = (const float*)d_in[1];
    const float* R0 = (const float*)d_in[2];
    const float* b0 = (const float*)d_in[3];
    const float* W1 = (const float*)d_in[4];
    const float* R1 = (const float*)d_in[5];
    const float* b1 = (const float*)d_in[6];
    const float* W2 = (const float*)d_in[7];
    const float* R2 = (const float*)d_in[8];
    const float* b2 = (const float*)d_in[9];
    const float* Wd = (const float*)d_in[10];
    const float* bd = (const float*)d_in[11];
    float* out = (float*)d_out;

    cudaFuncSetAttribute(k_lstm, cudaFuncAttributeMaxDynamicSharedMemorySize, LSTM_SMEM_BYTES);

    dim3 gemm_grid(NG / GBN, (B_ * T_) / GBM);

    // order: 0 t0, 1 gemm0(K=64), 2 lstm0, 3 gemm1(K=128) <- ncu capture slot,
    //        4 t1 is needed BEFORE lstm1, so: t1 early; keep deps correct:
    k_transpose_R<<<NG, U_>>>(R0, 0);
    k_gemm_xw<<<gemm_grid, 256>>>(x, W0, b0, F_);
    k_lstm<<<B_ / 2, 256, LSTM_SMEM_BYTES>>>(0);
    k_gemm_xw<<<gemm_grid, 256>>>(nullptr, W1, b1, U_);   // capture slot 3 (K=128)
    k_transpose_R<<<NG, U_>>>(R1, 1);
    k_lstm<<<B_ / 2, 256, LSTM_SMEM_BYTES>>>(1);
    k_gemm_xw<<<gemm_grid, 256>>>(nullptr, W2, b2, U_);
    k_transpose_R<<<NG, U_>>>(R2, 2);
    k_lstm<<<B_ / 2, 256, LSTM_SMEM_BYTES>>>(2);

    k_dense<<<(B_ * OUT_ + 255) / 256, 256>>>(Wd, bd, out);
}

// round 14
// speedup vs baseline: 1.4940x; 1.1965x over previous
#include <cuda_runtime.h>
#include <math.h>

// Problem constants
#define U_    128
#define NG    512
#define T_    512
#define B_    256
#define F_    64
#define OUT_  6

// LSTM R split (proven): 44 k-values in SMEM, 84 in registers
#define KSM   44
#define KRG   84
#define NQ_SM (KSM / 4)
#define NQ_RG (KRG / 4)

typedef unsigned long long ull;
typedef unsigned int uint32;

#define FMA2(acc, a, b) \
    asm("fma.rn.f32x2 %0, %1, %2, %0;" : "+l"(acc) \
        : "l"(__double_as_longlong(a)), "l"(__double_as_longlong(b)))

__device__ __forceinline__ float lo32(ull v) { return __int_as_float((int)(v & 0xffffffffull)); }
__device__ __forceinline__ float hi32(ull v) { return __int_as_float((int)(v >> 32)); }
__device__ __forceinline__ float unpack_sum(ull v) { return lo32(v) + hi32(v); }

__device__ __forceinline__ float fast_sigmoid(float x) {
    return __fdividef(1.f, 1.f + __expf(-x));
}
__device__ __forceinline__ float fast_tanh(float x) {
    float e = __expf(fminf(-2.f * x, 80.f));
    return __fdividef(1.f - e, 1.f + e);
}

__device__ __forceinline__ float f2tf(float f) {
    uint32 r;
    asm("cvt.rna.tf32.f32 %0, %1;" : "=r"(r) : "f"(f));
    return __uint_as_float(r);
}

// ---------------- scratch ----------------
__device__ float g_xw[(size_t)B_ * T_ * NG];
__device__ float g_h [(size_t)B_ * T_ * U_];
__device__ float g_RT[3][NG * U_];

// ---------------- R transpose ----------------
__global__ void k_transpose_R(const float* __restrict__ R, int layer) {
    int j = blockIdx.x;
    int k = threadIdx.x;
    g_RT[layer][j * U_ + k] = R[k * NG + j];
}

// ---------------- GEMM: tf32 tensor-core mma, 128x128x16 double-buffered ----------------
#define GBM 128
#define GBN 128
#define BK2 16
#define SPAD 8     // row stride 136 floats -> conflict-free fragment gathers
__global__ __launch_bounds__(256, 2) void k_gemm_xw(const float* __restrict__ Ain,
                                                    const float* __restrict__ W,
                                                    const float* __restrict__ bias,
                                                    int K) {
    const float* A = Ain ? Ain : g_h;
    __shared__ float As[2][BK2][GBM + SPAD];
    __shared__ float Bs[2][BK2][GBN + SPAD];
    const int brow = blockIdx.y * GBM;
    const int bcol = blockIdx.x * GBN;
    const int tid = threadIdx.x;
    const int wid = tid >> 5, lane = tid & 31;
    const int wm = wid >> 1, wn = wid & 1;     // 4x2 warp grid: warp tile 32x64
    const int grp = lane >> 2, tig = lane & 3;

    // global load mapping (same as R13)
    const int a_m = tid >> 1;
    const int a_k = (tid & 1) * 8;
    const int b_k = tid >> 5;
    const int b_n = (tid & 31) * 4;

    float c[2][8][4];
    #pragma unroll
    for (int mt = 0; mt < 2; mt++)
        #pragma unroll
        for (int nt = 0; nt < 8; nt++)
            #pragma unroll
            for (int i = 0; i < 4; i++) c[mt][nt][i] = 0.f;

    const float* a_ptr  = &A[(size_t)(brow + a_m) * K + a_k];
    const float* b_ptr0 = &W[(size_t)b_k * NG + bcol + b_n];
    const float* b_ptr1 = &W[(size_t)(b_k + 8) * NG + bcol + b_n];

    // prologue: k-block 0 -> buffer 0 (convert to tf32 at store)
    float4 ar0 = *reinterpret_cast<const float4*>(a_ptr);
    float4 ar1 = *reinterpret_cast<const float4*>(a_ptr + 4);
    float4 br0 = *reinterpret_cast<const float4*>(b_ptr0);
    float4 br1 = *reinterpret_cast<const float4*>(b_ptr1);
    As[0][a_k + 0][a_m] = f2tf(ar0.x); As[0][a_k + 1][a_m] = f2tf(ar0.y);
    As[0][a_k + 2][a_m] = f2tf(ar0.z); As[0][a_k + 3][a_m] = f2tf(ar0.w);
    As[0][a_k + 4][a_m] = f2tf(ar1.x); As[0][a_k + 5][a_m] = f2tf(ar1.y);
    As[0][a_k + 6][a_m] = f2tf(ar1.z); As[0][a_k + 7][a_m] = f2tf(ar1.w);
    {
        float4 t0 = make_float4(f2tf(br0.x), f2tf(br0.y), f2tf(br0.z), f2tf(br0.w));
        float4 t1 = make_float4(f2tf(br1.x), f2tf(br1.y), f2tf(br1.z), f2tf(br1.w));
        *reinterpret_cast<float4*>(&Bs[0][b_k][b_n])     = t0;
        *reinterpret_cast<float4*>(&Bs[0][b_k + 8][b_n]) = t1;
    }
    __syncthreads();

    const int nk = K / BK2;
    for (int kb = 0; kb < nk; kb++) {
        const int cur = kb & 1;
        const int nxt = cur ^ 1;
        if (kb + 1 < nk) {
            const int k0 = (kb + 1) * BK2;
            ar0 = *reinterpret_cast<const float4*>(a_ptr + k0);
            ar1 = *reinterpret_cast<const float4*>(a_ptr + k0 + 4);
            br0 = *reinterpret_cast<const float4*>(b_ptr0 + (size_t)k0 * NG);
            br1 = *reinterpret_cast<const float4*>(b_ptr1 + (size_t)k0 * NG);
        }

        #pragma unroll
        for (int ks = 0; ks < 2; ks++) {
            const int kk = ks * 8 + tig;
            // A fragments: 2 m-tiles x 4 regs
            uint32 afr[2][4];
            #pragma unroll
            for (int mt = 0; mt < 2; mt++) {
                const int r0 = wm * 32 + mt * 16 + grp;
                afr[mt][0] = __float_as_uint(As[cur][kk][r0]);
                afr[mt][1] = __float_as_uint(As[cur][kk][r0 + 8]);
                afr[mt][2] = __float_as_uint(As[cur][kk + 4][r0]);
                afr[mt][3] = __float_as_uint(As[cur][kk + 4][r0 + 8]);
            }
            // B fragments: 8 n-tiles x 2 regs
            uint32 bfr[8][2];
            #pragma unroll
            for (int nt = 0; nt < 8; nt++) {
                const int n0 = wn * 64 + nt * 8 + grp;
                bfr[nt][0] = __float_as_uint(Bs[cur][kk][n0]);
                bfr[nt][1] = __float_as_uint(Bs[cur][kk + 4][n0]);
            }
            #pragma unroll
            for (int mt = 0; mt < 2; mt++)
                #pragma unroll
                for (int nt = 0; nt < 8; nt++) {
                    asm volatile(
                        "mma.sync.aligned.m16n8k8.row.col.f32.tf32.tf32.f32 "
                        "{%0,%1,%2,%3}, {%4,%5,%6,%7}, {%8,%9}, {%0,%1,%2,%3};"
                        : "+f"(c[mt][nt][0]), "+f"(c[mt][nt][1]),
                          "+f"(c[mt][nt][2]), "+f"(c[mt][nt][3])
                        : "r"(afr[mt][0]), "r"(afr[mt][1]),
                          "r"(afr[mt][2]), "r"(afr[mt][3]),
                          "r"(bfr[nt][0]), "r"(bfr[nt][1]));
                }
        }

        if (kb + 1 < nk) {
            As[nxt][a_k + 0][a_m] = f2tf(ar0.x); As[nxt][a_k + 1][a_m] = f2tf(ar0.y);
            As[nxt][a_k + 2][a_m] = f2tf(ar0.z); As[nxt][a_k + 3][a_m] = f2tf(ar0.w);
            As[nxt][a_k + 4][a_m] = f2tf(ar1.x); As[nxt][a_k + 5][a_m] = f2tf(ar1.y);
            As[nxt][a_k + 6][a_m] = f2tf(ar1.z); As[nxt][a_k + 7][a_m] = f2tf(ar1.w);
            float4 t0 = make_float4(f2tf(br0.x), f2tf(br0.y), f2tf(br0.z), f2tf(br0.w));
            float4 t1 = make_float4(f2tf(br1.x), f2tf(br1.y), f2tf(br1.z), f2tf(br1.w));
            *reinterpret_cast<float4*>(&Bs[nxt][b_k][b_n])     = t0;
            *reinterpret_cast<float4*>(&Bs[nxt][b_k + 8][b_n]) = t1;
        }
        __syncthreads();
    }

    // epilogue: bias + store (fragment rows grp/grp+8, col pairs tig*2)
    #pragma unroll
    for (int nt = 0; nt < 8; nt++) {
        const int col = bcol + wn * 64 + nt * 8 + tig * 2;
        const float bb0 = bias[col], bb1 = bias[col + 1];
        #pragma unroll
        for (int mt = 0; mt < 2; mt++) {
            const size_t row0 = (size_t)(brow + wm * 32 + mt * 16 + grp);
            float2 o0 = make_float2(c[mt][nt][0] + bb0, c[mt][nt][1] + bb1);
            float2 o1 = make_float2(c[mt][nt][2] + bb0, c[mt][nt][3] + bb1);
            *reinterpret_cast<float2*>(&g_xw[row0 * NG + col])       = o0;
            *reinterpret_cast<float2*>(&g_xw[(row0 + 8) * NG + col]) = o1;
        }
    }
}

// ---------------- LSTM scan (R11/R13 exact) ----------------
#define LSTM_SMEM_FLOATS 30000
#define LSTM_SMEM_BYTES  (LSTM_SMEM_FLOATS * 4)

__global__ __launch_bounds__(256) void k_lstm(int layer) {
    extern __shared__ float smem[];
    float* sR   = smem;
    float* sh   = sR + NG * KSM;
    float* sc   = sh + 2 * U_;
    float* sact = sc + 2 * U_;

    const int tid = threadIdx.x;
    const int c0 = tid;
    const int c1 = tid + 256;
    const int b0 = blockIdx.x * 2;
    const float* RT = g_RT[layer];

    for (int i = tid; i < NG * KSM; i += 256) {
        int col = i / KSM, k = i - col * KSM;
        sR[i] = RT[col * U_ + k];
    }
    double rr0[NQ_RG * 2], rr1[NQ_RG * 2];
    {
        const double2* rg0 = reinterpret_cast<const double2*>(RT + c0 * U_ + KSM);
        const double2* rg1 = reinterpret_cast<const double2*>(RT + c1 * U_ + KSM);
        #pragma unroll
        for (int q = 0; q < NQ_RG; q++) {
            double2 v0 = rg0[q];
            double2 v1 = rg1[q];
            rr0[2 * q] = v0.x; rr0[2 * q + 1] = v0.y;
            rr1[2 * q] = v1.x; rr1[2 * q + 1] = v1.y;
        }
    }
    { sh[tid] = 0.f; sc[tid] = 0.f; }
    __syncthreads();

    const double2* rs0 = reinterpret_cast<const double2*>(sR + c0 * KSM);
    const double2* rs1 = reinterpret_cast<const double2*>(sR + c1 * KSM);
    const double2* h0p = reinterpret_cast<const double2*>(sh);
    const double2* h1p = reinterpret_cast<const double2*>(sh + U_);
    const size_t xw0base = (size_t)b0 * T_ * NG;
    const size_t xw1base = (size_t)(b0 + 1) * T_ * NG;

    float pf00 = __ldcs(&g_xw[xw0base + c0]);
    float pf01 = __ldcs(&g_xw[xw0base + c1]);
    float pf10 = __ldcs(&g_xw[xw1base + c0]);
    float pf11 = __ldcs(&g_xw[xw1base + c1]);

    for (int t = 0; t < T_; t++) {
        ull a00 = (ull)__float_as_uint(pf00);
        ull a01 = (ull)__float_as_uint(pf01);
        ull a10 = (ull)__float_as_uint(pf10);
        ull a11 = (ull)__float_as_uint(pf11);
        if (t + 1 < T_) {
            size_t o0 = xw0base + (size_t)(t + 1) * NG;
            size_t o1 = xw1base + (size_t)(t + 1) * NG;
            pf00 = __ldcs(&g_xw[o0 + c0]);
            pf01 = __ldcs(&g_xw[o0 + c1]);
            pf10 = __ldcs(&g_xw[o1 + c0]);
            pf11 = __ldcs(&g_xw[o1 + c1]);
        }

        #pragma unroll
        for (int q = 0; q < NQ_SM; q++) {
            double2 r0 = rs0[q];
            double2 r1 = rs1[q];
            double2 h0 = h0p[q];
            double2 h1 = h1p[q];
            FMA2(a00, r0.x, h0.x); FMA2(a01, r1.x, h0.x);
            FMA2(a10, r0.x, h1.x); FMA2(a11, r1.x, h1.x);
            FMA2(a00, r0.y, h0.y); FMA2(a01, r1.y, h0.y);
            FMA2(a10, r0.y, h1.y); FMA2(a11, r1.y, h1.y);
        }
        #pragma unroll
        for (int q = 0; q < NQ_RG; q++) {
            double2 h0 = h0p[NQ_SM + q];
            double2 h1 = h1p[NQ_SM + q];
            FMA2(a00, rr0[2 * q], h0.x); FMA2(a01, rr1[2 * q], h0.x);
            FMA2(a10, rr0[2 * q], h1.x); FMA2(a11, rr1[2 * q], h1.x);
            FMA2(a00, rr0[2 * q + 1], h0.y); FMA2(a01, rr1[2 * q + 1], h0.y);
            FMA2(a10, rr0[2 * q + 1], h1.y); FMA2(a11, rr1[2 * q + 1], h1.y);
        }

        float z00 = unpack_sum(a00);
        float z01 = unpack_sum(a01);
        float z10 = unpack_sum(a10);
        float z11 = unpack_sum(a11);

        float s00 = fast_sigmoid(z00);
        float s10 = fast_sigmoid(z10);
        float s01, s11;
        if (tid < 128) { s01 = fast_tanh(z01);    s11 = fast_tanh(z11); }
        else           { s01 = fast_sigmoid(z01); s11 = fast_sigmoid(z11); }

        sact[c0] = s00;        sact[c1] = s01;
        sact[NG + c0] = s10;   sact[NG + c1] = s11;
        __syncthreads();

        {
            int m = tid >> 7, u = tid & (U_ - 1);
            const float* s = sact + m * NG;
            float iv = s[u], fv = s[U_ + u], gv = s[2 * U_ + u], ov = s[3 * U_ + u];
            float c = fmaf(fv, sc[tid], iv * gv);
            float h = ov * fast_tanh(c);
            sc[tid] = c;
            sh[m * U_ + u] = h;
            g_h[((size_t)(b0 + m) * T_ + t) * U_ + u] = h;
        }
        __syncthreads();
    }
}

// ---------------- dense head ----------------
__global__ void k_dense(const float* __restrict__ Wd, const float* __restrict__ bd,
                        float* __restrict__ out) {
    int idx = blockIdx.x * 256 + threadIdx.x;
    if (idx >= B_ * OUT_) return;
    int b = idx / OUT_, j = idx % OUT_;
    const float* hrow = &g_h[((size_t)b * T_ + (T_ - 1)) * U_];
    float s = bd[j];
    #pragma unroll
    for (int k = 0; k < U_; k++) s = fmaf(hrow[k], Wd[k * OUT_ + j], s);
    out[idx] = s;
}

// ---------------- launch ----------------
extern "C" void kernel_launch(void* const* d_in, const int* in_sizes, int n_in,
                              void* d_out, int out_size) {
    const float* x  = (const float*)d_in[0];
    const float* W0 = (const float*)d_in[1];
    const float* R0 = (const float*)d_in[2];
    const float* b0 = (const float*)d_in[3];
    const float* W1 = (const float*)d_in[4];
    const float* R1 = (const float*)d_in[5];
    const float* b1 = (const float*)d_in[6];
    const float* W2 = (const float*)d_in[7];
    const float* R2 = (const float*)d_in[8];
    const float* b2 = (const float*)d_in[9];
    const float* Wd = (const float*)d_in[10];
    const float* bd = (const float*)d_in[11];
    float* out = (float*)d_out;

    cudaFuncSetAttribute(k_lstm, cudaFuncAttributeMaxDynamicSharedMemorySize, LSTM_SMEM_BYTES);

    dim3 gemm_grid(NG / GBN, (B_ * T_) / GBM);

    // order: 0 t0, 1 gemm0(K=64), 2 lstm0, 3 gemm1(K=128) <- ncu capture slot
    k_transpose_R<<<NG, U_>>>(R0, 0);
    k_gemm_xw<<<gemm_grid, 256>>>(x, W0, b0, F_);
    k_lstm<<<B_ / 2, 256, LSTM_SMEM_BYTES>>>(0);
    k_gemm_xw<<<gemm_grid, 256>>>(nullptr, W1, b1, U_);
    k_transpose_R<<<NG, U_>>>(R1, 1);
    k_lstm<<<B_ / 2, 256, LSTM_SMEM_BYTES>>>(1);
    k_gemm_xw<<<gemm_grid, 256>>>(nullptr, W2, b2, U_);
    k_transpose_R<<<NG, U_>>>(R2, 2);
    k_lstm<<<B_ / 2, 256, LSTM_SMEM_BYTES>>>(2);

    k_dense<<<(B_ * OUT_ + 255) / 256, 256>>>(Wd, bd, out);
}